// round 15
// baseline (speedup 1.0000x reference)
#include <cuda_runtime.h>
#include <cuda_bf16.h>
#include <cstdint>
#include <math.h>

#define NN 4096
#define HH 128
#define KM 32
#define KI 20
#define BB 32
#define SMP 132
#define NL 12

#define OFF_H    0
#define OFF_POS  (NN*HH)
#define OFF_F    (OFF_POS + NN*3)
#define OFF_S    (OFF_F + NN*3)
#define OFF_CONF (OFF_S + 3*NN*KI)
#define OFF_ST   (OFF_CONF + NN*64)

typedef unsigned long long ull;

__device__ float g_h[2][NN*HH];
__device__ float g_pos[2][NN*3];
__device__ float g_A[NN*HH];
__device__ float g_B[NN*HH];
__device__ float g_agg[NN*HH];
__device__ float g_dots[6][NN];
__device__ int   g_idx[NN*KM];
__device__ int   g_cnt[NN];
__device__ int   g_iidx[NN*KI];
__device__ int   g_icnt[NN];
__device__ int   g_seg[BB+1];
// fragment-packed bf16 weights, uint4-paired n-tiles (mats: ew2, cw1)
__device__ __align__(16) uint4 g_Wfrag[36*2048];

__device__ __forceinline__ float silu_f(float x) {
    return __fdividef(x, 1.0f + __expf(-x));
}

// ---- packed fp32x2 scalar GEMM helpers ----
__device__ __forceinline__ ull pack2(float x) {
    ull r; asm("mov.b64 %0, {%1, %1};" : "=l"(r) : "r"(__float_as_uint(x))); return r;
}
__device__ __forceinline__ void ffma2(ull& a, ull v, ull w) {
    asm("fma.rn.f32x2 %0, %1, %2, %0;" : "+l"(a) : "l"(v), "l"(w));
}
__device__ __forceinline__ float2 unpack2(ull a) {
    unsigned lo, hi; asm("mov.b64 {%0, %1}, %2;" : "=r"(lo), "=r"(hi) : "l"(a));
    return make_float2(__uint_as_float(lo), __uint_as_float(hi));
}
template<int NE2, int TP>
__device__ __forceinline__ void gemm_t(ull* acc, const float (*T)[TP],
                                       const float* __restrict__ W, int c, int kk) {
    #pragma unroll 4
    for (int k = 0; k < kk; k++) {
        ull w2 = pack2(W[k*HH + c]);
        const ulonglong2* r = reinterpret_cast<const ulonglong2*>(T[k]);
        #pragma unroll
        for (int q = 0; q < NE2; q++) {
            ulonglong2 v = r[q];
            ffma2(acc[2*q], v.x, w2); ffma2(acc[2*q+1], v.y, w2);
        }
    }
}
// half-tile: 4 node-columns at ulonglong2 offset eo (bit-identical q=eo slice)
template<int TP>
__device__ __forceinline__ void gemm_half(ull* acc, const float (*T)[TP],
                                          const float* __restrict__ W, int c, int eo) {
    #pragma unroll 4
    for (int k = 0; k < HH; k++) {
        ull w2 = pack2(W[k*HH + c]);
        const ulonglong2* r = reinterpret_cast<const ulonglong2*>(T[k]) + eo;
        ulonglong2 v = r[0];
        ffma2(acc[0], v.x, w2); ffma2(acc[1], v.y, w2);
    }
}

// ---- mma.sync helpers ----
__device__ __forceinline__ void mma_bf16(float* d, const uint32_t* a, uint32_t bx, uint32_t by) {
    asm volatile("mma.sync.aligned.m16n8k16.row.col.f32.bf16.bf16.f32 "
        "{%0,%1,%2,%3}, {%4,%5,%6,%7}, {%8,%9}, {%0,%1,%2,%3};"
        : "+f"(d[0]), "+f"(d[1]), "+f"(d[2]), "+f"(d[3])
        : "r"(a[0]), "r"(a[1]), "r"(a[2]), "r"(a[3]), "r"(bx), "r"(by));
}
__device__ __forceinline__ void split3x2(float x, float y,
                                         uint32_t& u0, uint32_t& u1, uint32_t& u2) {
    __nv_bfloat162 v0 = __floats2bfloat162_rn(x, y);
    float rx = x - __bfloat162float(v0.x), ry = y - __bfloat162float(v0.y);
    __nv_bfloat162 v1 = __floats2bfloat162_rn(rx, ry);
    rx -= __bfloat162float(v1.x); ry -= __bfloat162float(v1.y);
    __nv_bfloat162 v2 = __floats2bfloat162_rn(rx, ry);
    u0 = *reinterpret_cast<uint32_t*>(&v0);
    u1 = *reinterpret_cast<uint32_t*>(&v1);
    u2 = *reinterpret_cast<uint32_t*>(&v2);
}
__device__ __forceinline__ __nv_bfloat16 wpart3(float w, int part) {
    __nv_bfloat16 p0 = __float2bfloat16(w);
    if (part == 0) return p0;
    float r = w - __bfloat162float(p0);
    __nv_bfloat16 p1 = __float2bfloat16(r);
    if (part == 1) return p1;
    return __float2bfloat16(r - __bfloat162float(p1));
}
__device__ __forceinline__ void term16(float (*acc)[4], const uint32_t* a,
                                       const uint4* __restrict__ p) {
    #pragma unroll
    for (int np = 0; np < 8; np++) {
        uint4 b = __ldg(p + np*32);
        mma_bf16(acc[2*np],   a, b.x, b.y);
        mma_bf16(acc[2*np+1], a, b.z, b.w);
    }
}
__device__ __forceinline__ void gemm6(float (*acc)[4],
                                      const uint32_t* a0, const uint32_t* a1, const uint32_t* a2,
                                      const uint4* __restrict__ p0, const uint4* __restrict__ p1,
                                      const uint4* __restrict__ p2) {
    term16(acc, a0, p0);
    term16(acc, a0, p1);
    term16(acc, a1, p0);
    term16(acc, a0, p2);
    term16(acc, a1, p1);
    term16(acc, a2, p0);
}
__device__ __forceinline__ void gemm_sT(float (*acc)[4], const float* sT,
                                        int r0, int r1, int qt,
                                        const uint4* p0, const uint4* p1, const uint4* p2) {
    #pragma unroll
    for (int ks = 0; ks < 8; ks++) {
        int k0 = ks*16 + qt*2;
        float2 x00 = *reinterpret_cast<const float2*>(sT + r0*SMP + k0);
        float2 x10 = *reinterpret_cast<const float2*>(sT + r1*SMP + k0);
        float2 x08 = *reinterpret_cast<const float2*>(sT + r0*SMP + k0 + 8);
        float2 x18 = *reinterpret_cast<const float2*>(sT + r1*SMP + k0 + 8);
        uint32_t a0[4], a1[4], a2[4];
        split3x2(x00.x, x00.y, a0[0], a1[0], a2[0]);
        split3x2(x10.x, x10.y, a0[1], a1[1], a2[1]);
        split3x2(x08.x, x08.y, a0[2], a1[2], a2[2]);
        split3x2(x18.x, x18.y, a0[3], a1[3], a2[3]);
        gemm6(acc, a0, a1, a2, p0 + ks*256, p1 + ks*256, p2 + ks*256);
    }
}

// ---- warp-local neighbor search for node i (same math as neighbors_warp) ----
template<int KK>
__device__ __forceinline__ void nbr_search(int i, int lane, const float* __restrict__ p,
                                           const int* __restrict__ batch, float cutoff2,
                                           int* __restrict__ oi, int* __restrict__ oc) {
    int b = batch[i];
    int s0 = g_seg[b], s1 = g_seg[b+1];
    float px = p[3*i], py = p[3*i+1], pz = p[3*i+2];
    const ull KMAX = ~0ull;
    ull keys[NL];
    #pragma unroll
    for (int q = 0; q < NL; q++) {
        int j = s0 + lane + q*32;
        ull key = KMAX;
        if (j < s1 && j != i) {
            float dx = px - p[3*j], dy = py - p[3*j+1], dz = pz - p[3*j+2];
            float d2 = dx*dx + dy*dy + dz*dz;
            if (d2 <= cutoff2)
                key = ((ull)__float_as_uint(d2) << 32) | (unsigned)j;
        }
        keys[q] = key;
    }
    ull mymin = KMAX;
    #pragma unroll
    for (int q = 0; q < NL; q++) mymin = min(mymin, keys[q]);
    int myout = i;
    int cnt = 0;
    for (int e = 0; e < KK; e++) {
        ull mn = mymin;
        #pragma unroll
        for (int o = 16; o > 0; o >>= 1) {
            ull ot = __shfl_xor_sync(0xffffffffu, mn, o);
            mn = min(mn, ot);
        }
        if (mn == KMAX) break;
        if (lane == e) myout = (int)(unsigned)(mn & 0xffffffffu);
        cnt++;
        if (mymin == mn) {
            #pragma unroll
            for (int q = 0; q < NL; q++) if (keys[q] == mn) keys[q] = KMAX;
            mymin = KMAX;
            #pragma unroll
            for (int q = 0; q < NL; q++) mymin = min(mymin, keys[q]);
        }
    }
    if (lane < KK) oi[i*KK + lane] = myout;
    if (lane == 0) oc[i] = cnt;
}

// ---- weight prep ----
__global__ void wprep_kernel(const float* __restrict__ ew2, const float* __restrict__ cw1) {
    int b = blockIdx.x;            // b = (l*2+mat)*3+part, grid 36
    int part = b % 3, mat = (b / 3) % 2, l = b / 6;
    const float* W = (mat ? cw1 : ew2) + l * HH * HH;
    uint4* dst = g_Wfrag + (size_t)b * 2048;
    for (int idx = threadIdx.x; idx < 2048; idx += blockDim.x) {
        int lane = idx & 31, np = (idx >> 5) & 7, ks = idx >> 8;
        int quad = lane >> 2, qt = lane & 3;
        int k0 = ks*16 + qt*2;
        uint4 u;
        #pragma unroll
        for (int half = 0; half < 2; half++) {
            int n = (2*np + half)*8 + quad;
            __nv_bfloat162 v0, v1;
            v0.x = wpart3(W[k0*HH + n], part);     v0.y = wpart3(W[(k0+1)*HH + n], part);
            v1.x = wpart3(W[(k0+8)*HH + n], part); v1.y = wpart3(W[(k0+9)*HH + n], part);
            if (half == 0) { u.x = *reinterpret_cast<uint32_t*>(&v0); u.y = *reinterpret_cast<uint32_t*>(&v1); }
            else           { u.z = *reinterpret_cast<uint32_t*>(&v0); u.w = *reinterpret_cast<uint32_t*>(&v1); }
        }
        dst[idx] = u;
    }
}

__global__ void seg_kernel(const int* __restrict__ batch) {
    int b = threadIdx.x;
    if (b <= BB) {
        int lo = 0, hi = NN;
        while (lo < hi) { int mid = (lo + hi) >> 1; if (batch[mid] < b) lo = mid + 1; else hi = mid; }
        g_seg[b] = lo;
    }
}
__global__ void init_copy(const float* __restrict__ h, const float* __restrict__ p) {
    int i = blockIdx.x * blockDim.x + threadIdx.x;
    if (i < NN*HH) g_h[0][i] = h[i];
    if (i < NN*3)  g_pos[0][i] = p[i];
}

// ---- standalone warp-per-node radius graph (final KI search only) ----
template<int KK, bool INTER>
__global__ __launch_bounds__(128) void neighbors_warp(int sel, const int* __restrict__ batch,
                                                      float cutoff2) {
    const int i = blockIdx.x * 4 + (threadIdx.x >> 5);
    const int lane = threadIdx.x & 31;
    if (i >= NN) return;
    nbr_search<KK>(i, lane, g_pos[sel], batch, cutoff2,
                   INTER ? g_iidx : g_idx, INTER ? g_icnt : g_cnt);
}

// ---- fused node(l)+pre(l+1): node split by wg over node-columns (bit-identical) ----
// mode: 0 = pre only, 1 = node+pre, 2 = node only
__global__ __launch_bounds__(256) void nodepre_kernel(
    int sel, int mode,
    const float* __restrict__ nw1, const float* __restrict__ nb1,
    const float* __restrict__ nw2, const float* __restrict__ nb2,
    const float* __restrict__ ew1, const float* __restrict__ eb1)
{
    int n0 = blockIdx.x * 8;
    int tid = threadIdx.x;
    int c = tid & 127, wg = tid >> 7;
    const float* h_in = g_h[sel];
    float* h_out = g_h[sel^1];
    __shared__ __align__(16) float s_hT[HH][12];
    __shared__ __align__(16) float s_aT[HH][12];

    #pragma unroll
    for (int e = 0; e < 4; e++) s_hT[c][wg*4 + e] = h_in[(n0 + wg*4 + e)*HH + c];
    if (mode != 0) {
        #pragma unroll
        for (int e = 0; e < 4; e++) s_aT[c][wg*4 + e] = g_agg[(n0 + wg*4 + e)*HH + c];
    }
    __syncthreads();

    if (mode != 0) {
        ull acc[2];
        ull b2 = pack2(nb1[c]);
        acc[0] = b2; acc[1] = b2;
        gemm_half<12>(acc, s_hT, nw1, c, wg);
        gemm_half<12>(acc, s_aT, nw1 + HH*HH, c, wg);
        __syncthreads();
        float2 f0 = unpack2(acc[0]), f1 = unpack2(acc[1]);
        s_aT[c][wg*4+0] = silu_f(f0.x); s_aT[c][wg*4+1] = silu_f(f0.y);
        s_aT[c][wg*4+2] = silu_f(f1.x); s_aT[c][wg*4+3] = silu_f(f1.y);
        __syncthreads();
        b2 = pack2(nb2[c]);
        acc[0] = b2; acc[1] = b2;
        gemm_half<12>(acc, s_aT, nw2, c, wg);
        f0 = unpack2(acc[0]); f1 = unpack2(acc[1]);
        float hv[4];
        hv[0] = s_hT[c][wg*4+0] + f0.x; hv[1] = s_hT[c][wg*4+1] + f0.y;
        hv[2] = s_hT[c][wg*4+2] + f1.x; hv[3] = s_hT[c][wg*4+3] + f1.y;
        #pragma unroll
        for (int e = 0; e < 4; e++) {
            h_out[(n0 + wg*4 + e)*HH + c] = hv[e];
            s_hT[c][wg*4 + e] = hv[e];
        }
        __syncthreads();
    }

    if (mode != 2) {
        ull acc[4];
        ull b2 = wg ? pack2(0.0f) : pack2(eb1[c]);
        #pragma unroll
        for (int q = 0; q < 4; q++) acc[q] = b2;
        gemm_t<2,12>(acc, s_hT, ew1 + wg*HH*HH, c, HH);
        float* outp = wg ? g_B : g_A;
        #pragma unroll
        for (int p = 0; p < 4; p++) {
            float2 f = unpack2(acc[p]);
            outp[(n0+2*p)*HH + c] = f.x; outp[(n0+2*p+1)*HH + c] = f.y;
        }
    }
}

// ---- edge kernel: 4 nodes/CTA, optional in-kernel neighbor rebuild ----
#define EDGE_DSM (128*SMP*4)

__global__ __launch_bounds__(256) void edge_mma_kernel(
    int sel, int layer, int do_nbr, float cutoff2,
    const int* __restrict__ batch,
    const float* __restrict__ ew1d, const float* __restrict__ eb2,
    const float* __restrict__ cb1,  const float* __restrict__ cw2)
{
    extern __shared__ float sM[];
    __shared__ int   sJ[128], sCnt[4];
    __shared__ float sMask[128], sD2[128], sRel[3*128];
    __shared__ float sWD[128], sEB2[128], sCB1[128], sCW2[128];
    __shared__ float sAgg[8][128];
    __shared__ float sCE[128];

    const int blk = blockIdx.x, tid = threadIdx.x;
    const int w = tid >> 5, lane = tid & 31, quad = lane >> 2, qt = lane & 3;
    const int nid = w & 3, half = w >> 2;
    const int r0 = (nid << 5) + (half << 4) + quad, r1 = r0 + 8;
    const float* p_in = g_pos[sel];
    float* p_out = g_pos[sel^1];

    // even layers: rebuild neighbor lists for this CTA's 4 nodes (warps 0-3)
    if (do_nbr && w < 4)
        nbr_search<KM>(4*blk + w, lane, p_in, batch, cutoff2, g_idx, g_cnt);
    // stage small per-layer vectors (warps 4-7 while 0-3 search)
    if (tid >= 128) {
        int x = tid - 128;
        sWD[x] = ew1d[x]; sEB2[x] = eb2[x]; sCB1[x] = cb1[x]; sCW2[x] = cw2[x];
    }
    __syncthreads();   // orders g_idx/g_cnt global writes within CTA

    if (tid < 4) sCnt[tid] = g_cnt[4*blk + tid];
    if (tid < 128) {
        int n = tid >> 5, e = tid & 31, i = 4*blk + n;
        int cnt = g_cnt[i];
        int j = (e < cnt) ? g_idx[i*KM + e] : i;
        sJ[tid] = j;
        sMask[tid] = (e < cnt) ? 1.0f : 0.0f;
        float rx = p_in[3*i] - p_in[3*j], ry = p_in[3*i+1] - p_in[3*j+1], rz = p_in[3*i+2] - p_in[3*j+2];
        sRel[tid] = rx; sRel[128+tid] = ry; sRel[256+tid] = rz;
        sD2[tid] = rx*rx + ry*ry + rz*rz;
    }
    __syncthreads();

    const bool live = sCnt[nid] > half * 16;
    if (live) {
        const int iNode = 4*blk + nid;
        const int j0 = sJ[r0], j1 = sJ[r1];
        const float d20 = sD2[r0], d21 = sD2[r1];
        const float mk0 = sMask[r0], mk1 = sMask[r1];
        const float* gAi = g_A + (size_t)iNode*HH;
        const float* gB0 = g_B + (size_t)j0*HH;
        const float* gB1 = g_B + (size_t)j1*HH;

        const uint4* Wg = g_Wfrag + (size_t)layer*6*2048;
        const uint4* W1p0 = Wg + lane;
        const uint4* W1p1 = Wg + 2048 + lane;
        const uint4* W1p2 = Wg + 2*2048 + lane;
        const uint4* W2p0 = Wg + 3*2048 + lane;
        const uint4* W2p1 = Wg + 4*2048 + lane;
        const uint4* W2p2 = Wg + 5*2048 + lane;

        float acc[16][4];
        #pragma unroll
        for (int nt = 0; nt < 16; nt++) { acc[nt][0]=0.f; acc[nt][1]=0.f; acc[nt][2]=0.f; acc[nt][3]=0.f; }

        #pragma unroll
        for (int ks = 0; ks < 8; ks++) {
            int base = ks*16 + qt*2;
            float2 A0 = *reinterpret_cast<const float2*>(gAi + base);
            float2 A8 = *reinterpret_cast<const float2*>(gAi + base + 8);
            float2 B00 = *reinterpret_cast<const float2*>(gB0 + base);
            float2 B08 = *reinterpret_cast<const float2*>(gB0 + base + 8);
            float2 B10 = *reinterpret_cast<const float2*>(gB1 + base);
            float2 B18 = *reinterpret_cast<const float2*>(gB1 + base + 8);
            float2 w0 = *reinterpret_cast<const float2*>(sWD + base);
            float2 w8 = *reinterpret_cast<const float2*>(sWD + base + 8);
            uint32_t a0[4], a1[4], a2[4];
            split3x2(silu_f(fmaf(d20, w0.x, A0.x + B00.x)), silu_f(fmaf(d20, w0.y, A0.y + B00.y)), a0[0], a1[0], a2[0]);
            split3x2(silu_f(fmaf(d21, w0.x, A0.x + B10.x)), silu_f(fmaf(d21, w0.y, A0.y + B10.y)), a0[1], a1[1], a2[1]);
            split3x2(silu_f(fmaf(d20, w8.x, A8.x + B08.x)), silu_f(fmaf(d20, w8.y, A8.y + B08.y)), a0[2], a1[2], a2[2]);
            split3x2(silu_f(fmaf(d21, w8.x, A8.x + B18.x)), silu_f(fmaf(d21, w8.y, A8.y + B18.y)), a0[3], a1[3], a2[3]);
            gemm6(acc, a0, a1, a2, W1p0 + ks*256, W1p1 + ks*256, W1p2 + ks*256);
        }

        #pragma unroll
        for (int nt = 0; nt < 16; nt++) {
            int cc = nt*8 + qt*2;
            float m00 = silu_f(acc[nt][0] + sEB2[cc])   * mk0;
            float m01 = silu_f(acc[nt][1] + sEB2[cc+1]) * mk0;
            float m10 = silu_f(acc[nt][2] + sEB2[cc])   * mk1;
            float m11 = silu_f(acc[nt][3] + sEB2[cc+1]) * mk1;
            sM[r0*SMP + cc]   = m00; sM[r0*SMP + cc+1] = m01;
            sM[r1*SMP + cc]   = m10; sM[r1*SMP + cc+1] = m11;
            float s0 = m00 + m10, s1 = m01 + m11;
            #pragma unroll
            for (int off = 4; off <= 16; off <<= 1) {
                s0 += __shfl_xor_sync(0xffffffffu, s0, off);
                s1 += __shfl_xor_sync(0xffffffffu, s1, off);
            }
            if (quad == 0) { sAgg[w][cc] = s0; sAgg[w][cc+1] = s1; }
            acc[nt][0] = 0.f; acc[nt][1] = 0.f; acc[nt][2] = 0.f; acc[nt][3] = 0.f;
        }

        gemm_sT(acc, sM, r0, r1, qt, W2p0, W2p1, W2p2);

        float p0 = 0.f, p1 = 0.f;
        #pragma unroll
        for (int nt = 0; nt < 16; nt++) {
            int cc = nt*8 + qt*2;
            p0 += silu_f(acc[nt][0] + sCB1[cc])*sCW2[cc] + silu_f(acc[nt][1] + sCB1[cc+1])*sCW2[cc+1];
            p1 += silu_f(acc[nt][2] + sCB1[cc])*sCW2[cc] + silu_f(acc[nt][3] + sCB1[cc+1])*sCW2[cc+1];
        }
        p0 += __shfl_xor_sync(0xffffffffu, p0, 1); p0 += __shfl_xor_sync(0xffffffffu, p0, 2);
        p1 += __shfl_xor_sync(0xffffffffu, p1, 1); p1 += __shfl_xor_sync(0xffffffffu, p1, 2);
        if (qt == 0) { sCE[r0] = p0; sCE[r1] = p1; }
    } else {
        for (int x = lane; x < 128; x += 32) sAgg[w][x] = 0.f;
        if (qt == 0) { sCE[r0] = 0.f; sCE[r1] = 0.f; }
    }
    __syncthreads();

    #pragma unroll
    for (int rep = 0; rep < 2; rep++) {
        int idx = tid + 256*rep;
        int n = idx >> 7, c = idx & 127;
        g_agg[(4*blk + n)*HH + c] = sAgg[n][c] + sAgg[n+4][c];
    }

    if (w < 4) {
        int r = 32*w + lane, i = 4*blk + w;
        float ce = sCE[r], mk = sMask[r];
        float fx = sRel[r]*ce*mk, fy = sRel[128+r]*ce*mk, fz = sRel[256+r]*ce*mk;
        #pragma unroll
        for (int o = 16; o > 0; o >>= 1) {
            fx += __shfl_down_sync(0xffffffffu, fx, o);
            fy += __shfl_down_sync(0xffffffffu, fy, o);
            fz += __shfl_down_sync(0xffffffffu, fz, o);
        }
        if (lane == 0) {
            float cnt = fmaxf((float)g_cnt[i], 1.0f);
            p_out[3*i+0] = p_in[3*i+0] + fx / cnt;
            p_out[3*i+1] = p_in[3*i+1] + fy / cnt;
            p_out[3*i+2] = p_in[3*i+2] + fz / cnt;
        }
    }
}

// ---- final readout (TILE=32) ----
__global__ __launch_bounds__(HH) void final_tile_kernel(
    const float* __restrict__ fw1, const float* __restrict__ fb1,
    const float* __restrict__ fw2, const float* __restrict__ fb2,
    const float* __restrict__ ccw1, const float* __restrict__ ccb1,
    const float* __restrict__ ccw2, const float* __restrict__ ccb2,
    const float* __restrict__ sw,  const float* __restrict__ sb,
    const float* __restrict__ iw,
    float* __restrict__ out)
{
    int n0 = blockIdx.x * 32, c = threadIdx.x;
    const float* h = g_h[0];
    const float* p = g_pos[0];
    __shared__ __align__(16) float s_hT[HH][36];
    __shared__ __align__(16) float s_tT[HH][36];

    #pragma unroll
    for (int e = 0; e < 32; e++) {
        float v = h[(n0+e)*HH + c];
        s_hT[c][e] = v;
        out[OFF_H + (n0+e)*HH + c] = v;
    }
    if (c < 3)
        for (int e = 0; e < 32; e++) out[OFF_POS + (n0+e)*3 + c] = p[(n0+e)*3 + c];
    __syncthreads();

    ull acc[16];
    ull b2 = pack2(fb1[c]);
    #pragma unroll
    for (int q = 0; q < 16; q++) acc[q] = b2;
    gemm_t<8,36>(acc, s_hT, fw1, c, HH);
    #pragma unroll
    for (int p2 = 0; p2 < 16; p2++) {
        float2 f = unpack2(acc[p2]);
        s_tT[c][2*p2] = tanhf(f.x); s_tT[c][2*p2+1] = tanhf(f.y);
    }
    __syncthreads();
    if (c < 96) {
        int e = c / 3, t = c % 3;
        float s = 0.0f;
        #pragma unroll 8
        for (int k = 0; k < HH; k++) s += s_tT[k][e] * fw2[k*3 + t];
        out[OFF_F + (n0+e)*3 + t] = s + fb2[t];
    }
    if (c < 32) {
        float s = 0.0f;
        #pragma unroll 8
        for (int k = 0; k < HH; k++) s += s_hT[k][c] * sw[k];
        out[OFF_ST + n0 + c] = s + sb[0];
        #pragma unroll
        for (int t = 0; t < 3; t++) {
            float da = 0.0f, db = 0.0f;
            const float* iwt = iw + t*258;
            #pragma unroll 8
            for (int k = 0; k < HH; k++) {
                float hv = s_hT[k][c];
                da += hv * iwt[k]; db += hv * iwt[128 + k];
            }
            g_dots[t][n0 + c] = da; g_dots[3+t][n0 + c] = db;
        }
    }
    __syncthreads();

    b2 = pack2(ccb1[c]);
    #pragma unroll
    for (int q = 0; q < 16; q++) acc[q] = b2;
    gemm_t<8,36>(acc, s_hT, ccw1, c, HH);
    #pragma unroll
    for (int p2 = 0; p2 < 16; p2++) {
        float2 f = unpack2(acc[p2]);
        s_tT[c][2*p2] = fmaxf(f.x, 0.0f); s_tT[c][2*p2+1] = fmaxf(f.y, 0.0f);
    }
    __syncthreads();
    if (c < 64) {
        ull bb = pack2(ccb2[c]);
        #pragma unroll
        for (int q = 0; q < 16; q++) acc[q] = bb;
        #pragma unroll 4
        for (int k = 0; k < HH; k++) {
            ull w2 = pack2(ccw2[k*64 + c]);
            const ulonglong2* r = reinterpret_cast<const ulonglong2*>(s_tT[k]);
            #pragma unroll
            for (int q = 0; q < 8; q++) {
                ulonglong2 v = r[q];
                ffma2(acc[2*q], v.x, w2); ffma2(acc[2*q+1], v.y, w2);
            }
        }
        #pragma unroll
        for (int p2 = 0; p2 < 16; p2++) {
            float2 f = unpack2(acc[p2]);
            out[OFF_CONF + (n0+2*p2)*64 + c]   = f.x;
            out[OFF_CONF + (n0+2*p2+1)*64 + c] = f.y;
        }
    }
}

__global__ void scores_kernel(const float* __restrict__ iw, const float* __restrict__ ib,
                              float* __restrict__ out) {
    int idx = blockIdx.x * blockDim.x + threadIdx.x;
    if (idx >= NN*KI) return;
    int i = idx / KI, e = idx % KI;
    const float* p = g_pos[0];
    int cnt = g_icnt[i];
    int j = g_iidx[i*KI + e];
    float mask = (e < cnt) ? 1.0f : 0.0f;
    float dx = p[3*i]-p[3*j], dy = p[3*i+1]-p[3*j+1], dz = p[3*i+2]-p[3*j+2];
    float dist = sqrtf(dx*dx + dy*dy + dz*dz + 1e-12f);
    #pragma unroll
    for (int t = 0; t < 3; t++) {
        const float* iwt = iw + t*258;
        float x = g_dots[t][i] + g_dots[3+t][j] + dist*iwt[256] + (dist/10.0f)*iwt[257] + ib[t];
        out[OFF_S + t*(NN*KI) + i*KI + e] = __fdividef(1.0f, 1.0f + __expf(-x)) * mask;
    }
}

extern "C" void kernel_launch(void* const* d_in, const int* in_sizes, int n_in,
                              void* d_out, int out_size)
{
    const float* h     = (const float*)d_in[0];
    const float* pos   = (const float*)d_in[1];
    const int*   batch = (const int*)  d_in[2];
    const float* ew1   = (const float*)d_in[3];
    const float* eb1   = (const float*)d_in[4];
    const float* ew2   = (const float*)d_in[5];
    const float* eb2   = (const float*)d_in[6];
    const float* cw1   = (const float*)d_in[7];
    const float* cb1   = (const float*)d_in[8];
    const float* cw2   = (const float*)d_in[9];
    const float* nw1   = (const float*)d_in[10];
    const float* nb1   = (const float*)d_in[11];
    const float* nw2   = (const float*)d_in[12];
    const float* nb2   = (const float*)d_in[13];
    const float* fw1   = (const float*)d_in[14];
    const float* fb1   = (const float*)d_in[15];
    const float* fw2   = (const float*)d_in[16];
    const float* fb2   = (const float*)d_in[17];
    const float* iw    = (const float*)d_in[18];
    const float* ib    = (const float*)d_in[19];
    const float* ccw1  = (const float*)d_in[20];
    const float* ccb1  = (const float*)d_in[21];
    const float* ccw2  = (const float*)d_in[22];
    const float* ccb2  = (const float*)d_in[23];
    const float* sw    = (const float*)d_in[24];
    const float* sb    = (const float*)d_in[25];
    float* out = (float*)d_out;

    cudaFuncSetAttribute(edge_mma_kernel, cudaFuncAttributeMaxDynamicSharedMemorySize, EDGE_DSM);

    seg_kernel<<<1, 64>>>(batch);
    init_copy<<<(NN*HH + 255)/256, 256>>>(h, pos);
    wprep_kernel<<<36, 256>>>(ew2, cw1);

    const float cut2[3] = {9.0f, 36.0f, 100.0f};
    int sel = 0;
    nodepre_kernel<<<NN/8, 256>>>(0, 0, nw1, nb1, nw2, nb2, ew1, eb1);   // layer 0 pre
    for (int l = 0; l < 6; l++) {
        int do_nbr = ((l & 1) == 0) ? 1 : 0;
        edge_mma_kernel<<<NN/4, 256, EDGE_DSM>>>(sel, l, do_nbr, cut2[l/2], batch,
                                                 ew1 + l*257*HH + 256*HH,
                                                 eb2 + l*HH, cb1 + l*HH, cw2 + l*HH);
        int mode = (l < 5) ? 1 : 2;
        int lp = (l < 5) ? l + 1 : 0;
        nodepre_kernel<<<NN/8, 256>>>(sel, mode,
                                      nw1 + l*256*HH, nb1 + l*HH,
                                      nw2 + l*HH*HH,  nb2 + l*HH,
                                      ew1 + lp*257*HH, eb1 + lp*HH);
        sel ^= 1;
    }
    neighbors_warp<KI, true><<<NN/4, 128>>>(0, batch, 100.0f);
    final_tile_kernel<<<NN/32, HH>>>(fw1, fb1, fw2, fb2,
                                     ccw1, ccb1, ccw2, ccb2, sw, sb, iw, out);
    scores_kernel<<<(NN*KI + 255)/256, 256>>>(iw, ib, out);
}

// round 16
// speedup vs baseline: 1.0471x; 1.0471x over previous
#include <cuda_runtime.h>
#include <cuda_bf16.h>
#include <cstdint>
#include <math.h>

#define NN 4096
#define HH 128
#define KM 32
#define KI 20
#define BB 32
#define SMP 132
#define NL 12

#define OFF_H    0
#define OFF_POS  (NN*HH)
#define OFF_F    (OFF_POS + NN*3)
#define OFF_S    (OFF_F + NN*3)
#define OFF_CONF (OFF_S + 3*NN*KI)
#define OFF_ST   (OFF_CONF + NN*64)

typedef unsigned long long ull;

__device__ float g_h[2][NN*HH];
__device__ float g_pos[2][NN*3];
__device__ float g_A[NN*HH];
__device__ float g_B[NN*HH];
__device__ float g_agg[NN*HH];
__device__ float g_dots[6][NN];
__device__ int   g_idx[NN*KM];
__device__ int   g_cnt[NN];
__device__ int   g_iidx[NN*KI];
__device__ int   g_icnt[NN];
__device__ int   g_seg[BB+1];
// fragment-packed bf16 weights, uint4-paired n-tiles (mats: ew2, cw1)
__device__ __align__(16) uint4 g_Wfrag[36*2048];

__device__ __forceinline__ float silu_f(float x) {
    return __fdividef(x, 1.0f + __expf(-x));
}

// ---- packed fp32x2 scalar GEMM helpers ----
__device__ __forceinline__ ull pack2(float x) {
    ull r; asm("mov.b64 %0, {%1, %1};" : "=l"(r) : "r"(__float_as_uint(x))); return r;
}
__device__ __forceinline__ void ffma2(ull& a, ull v, ull w) {
    asm("fma.rn.f32x2 %0, %1, %2, %0;" : "+l"(a) : "l"(v), "l"(w));
}
__device__ __forceinline__ float2 unpack2(ull a) {
    unsigned lo, hi; asm("mov.b64 {%0, %1}, %2;" : "=r"(lo), "=r"(hi) : "l"(a));
    return make_float2(__uint_as_float(lo), __uint_as_float(hi));
}
template<int NE2, int TP>
__device__ __forceinline__ void gemm_t(ull* acc, const float (*T)[TP],
                                       const float* __restrict__ W, int c, int kk) {
    #pragma unroll 4
    for (int k = 0; k < kk; k++) {
        ull w2 = pack2(W[k*HH + c]);
        const ulonglong2* r = reinterpret_cast<const ulonglong2*>(T[k]);
        #pragma unroll
        for (int q = 0; q < NE2; q++) {
            ulonglong2 v = r[q];
            ffma2(acc[2*q], v.x, w2); ffma2(acc[2*q+1], v.y, w2);
        }
    }
}
// half-tile: 4 node-columns at ulonglong2 offset eo (bit-identical q=eo slice)
template<int TP>
__device__ __forceinline__ void gemm_half(ull* acc, const float (*T)[TP],
                                          const float* __restrict__ W, int c, int eo) {
    #pragma unroll 4
    for (int k = 0; k < HH; k++) {
        ull w2 = pack2(W[k*HH + c]);
        const ulonglong2* r = reinterpret_cast<const ulonglong2*>(T[k]) + eo;
        ulonglong2 v = r[0];
        ffma2(acc[0], v.x, w2); ffma2(acc[1], v.y, w2);
    }
}

// ---- mma.sync helpers ----
__device__ __forceinline__ void mma_bf16(float* d, const uint32_t* a, uint32_t bx, uint32_t by) {
    asm volatile("mma.sync.aligned.m16n8k16.row.col.f32.bf16.bf16.f32 "
        "{%0,%1,%2,%3}, {%4,%5,%6,%7}, {%8,%9}, {%0,%1,%2,%3};"
        : "+f"(d[0]), "+f"(d[1]), "+f"(d[2]), "+f"(d[3])
        : "r"(a[0]), "r"(a[1]), "r"(a[2]), "r"(a[3]), "r"(bx), "r"(by));
}
__device__ __forceinline__ void split3x2(float x, float y,
                                         uint32_t& u0, uint32_t& u1, uint32_t& u2) {
    __nv_bfloat162 v0 = __floats2bfloat162_rn(x, y);
    float rx = x - __bfloat162float(v0.x), ry = y - __bfloat162float(v0.y);
    __nv_bfloat162 v1 = __floats2bfloat162_rn(rx, ry);
    rx -= __bfloat162float(v1.x); ry -= __bfloat162float(v1.y);
    __nv_bfloat162 v2 = __floats2bfloat162_rn(rx, ry);
    u0 = *reinterpret_cast<uint32_t*>(&v0);
    u1 = *reinterpret_cast<uint32_t*>(&v1);
    u2 = *reinterpret_cast<uint32_t*>(&v2);
}
__device__ __forceinline__ __nv_bfloat16 wpart3(float w, int part) {
    __nv_bfloat16 p0 = __float2bfloat16(w);
    if (part == 0) return p0;
    float r = w - __bfloat162float(p0);
    __nv_bfloat16 p1 = __float2bfloat16(r);
    if (part == 1) return p1;
    return __float2bfloat16(r - __bfloat162float(p1));
}
__device__ __forceinline__ void term16(float (*acc)[4], const uint32_t* a,
                                       const uint4* __restrict__ p) {
    #pragma unroll
    for (int np = 0; np < 8; np++) {
        uint4 b = __ldg(p + np*32);
        mma_bf16(acc[2*np],   a, b.x, b.y);
        mma_bf16(acc[2*np+1], a, b.z, b.w);
    }
}
__device__ __forceinline__ void gemm6(float (*acc)[4],
                                      const uint32_t* a0, const uint32_t* a1, const uint32_t* a2,
                                      const uint4* __restrict__ p0, const uint4* __restrict__ p1,
                                      const uint4* __restrict__ p2) {
    term16(acc, a0, p0);
    term16(acc, a0, p1);
    term16(acc, a1, p0);
    term16(acc, a0, p2);
    term16(acc, a1, p1);
    term16(acc, a2, p0);
}
__device__ __forceinline__ void gemm_sT(float (*acc)[4], const float* sT,
                                        int r0, int r1, int qt,
                                        const uint4* p0, const uint4* p1, const uint4* p2) {
    #pragma unroll
    for (int ks = 0; ks < 8; ks++) {
        int k0 = ks*16 + qt*2;
        float2 x00 = *reinterpret_cast<const float2*>(sT + r0*SMP + k0);
        float2 x10 = *reinterpret_cast<const float2*>(sT + r1*SMP + k0);
        float2 x08 = *reinterpret_cast<const float2*>(sT + r0*SMP + k0 + 8);
        float2 x18 = *reinterpret_cast<const float2*>(sT + r1*SMP + k0 + 8);
        uint32_t a0[4], a1[4], a2[4];
        split3x2(x00.x, x00.y, a0[0], a1[0], a2[0]);
        split3x2(x10.x, x10.y, a0[1], a1[1], a2[1]);
        split3x2(x08.x, x08.y, a0[2], a1[2], a2[2]);
        split3x2(x18.x, x18.y, a0[3], a1[3], a2[3]);
        gemm6(acc, a0, a1, a2, p0 + ks*256, p1 + ks*256, p2 + ks*256);
    }
}

// ---- warp-local neighbor search for node i ----
template<int KK>
__device__ __forceinline__ void nbr_search(int i, int lane, const float* __restrict__ p,
                                           const int* __restrict__ batch, float cutoff2,
                                           int* __restrict__ oi, int* __restrict__ oc) {
    int b = batch[i];
    int s0 = g_seg[b], s1 = g_seg[b+1];
    float px = p[3*i], py = p[3*i+1], pz = p[3*i+2];
    const ull KMAX = ~0ull;
    ull keys[NL];
    #pragma unroll
    for (int q = 0; q < NL; q++) {
        int j = s0 + lane + q*32;
        ull key = KMAX;
        if (j < s1 && j != i) {
            float dx = px - p[3*j], dy = py - p[3*j+1], dz = pz - p[3*j+2];
            float d2 = dx*dx + dy*dy + dz*dz;
            if (d2 <= cutoff2)
                key = ((ull)__float_as_uint(d2) << 32) | (unsigned)j;
        }
        keys[q] = key;
    }
    ull mymin = KMAX;
    #pragma unroll
    for (int q = 0; q < NL; q++) mymin = min(mymin, keys[q]);
    int myout = i;
    int cnt = 0;
    for (int e = 0; e < KK; e++) {
        ull mn = mymin;
        #pragma unroll
        for (int o = 16; o > 0; o >>= 1) {
            ull ot = __shfl_xor_sync(0xffffffffu, mn, o);
            mn = min(mn, ot);
        }
        if (mn == KMAX) break;
        if (lane == e) myout = (int)(unsigned)(mn & 0xffffffffu);
        cnt++;
        if (mymin == mn) {
            #pragma unroll
            for (int q = 0; q < NL; q++) if (keys[q] == mn) keys[q] = KMAX;
            mymin = KMAX;
            #pragma unroll
            for (int q = 0; q < NL; q++) mymin = min(mymin, keys[q]);
        }
    }
    if (lane < KK) oi[i*KK + lane] = myout;
    if (lane == 0) oc[i] = cnt;
}

// ---- weight prep ----
__global__ void wprep_kernel(const float* __restrict__ ew2, const float* __restrict__ cw1) {
    int b = blockIdx.x;            // b = (l*2+mat)*3+part, grid 36
    int part = b % 3, mat = (b / 3) % 2, l = b / 6;
    const float* W = (mat ? cw1 : ew2) + l * HH * HH;
    uint4* dst = g_Wfrag + (size_t)b * 2048;
    for (int idx = threadIdx.x; idx < 2048; idx += blockDim.x) {
        int lane = idx & 31, np = (idx >> 5) & 7, ks = idx >> 8;
        int quad = lane >> 2, qt = lane & 3;
        int k0 = ks*16 + qt*2;
        uint4 u;
        #pragma unroll
        for (int half = 0; half < 2; half++) {
            int n = (2*np + half)*8 + quad;
            __nv_bfloat162 v0, v1;
            v0.x = wpart3(W[k0*HH + n], part);     v0.y = wpart3(W[(k0+1)*HH + n], part);
            v1.x = wpart3(W[(k0+8)*HH + n], part); v1.y = wpart3(W[(k0+9)*HH + n], part);
            if (half == 0) { u.x = *reinterpret_cast<uint32_t*>(&v0); u.y = *reinterpret_cast<uint32_t*>(&v1); }
            else           { u.z = *reinterpret_cast<uint32_t*>(&v0); u.w = *reinterpret_cast<uint32_t*>(&v1); }
        }
        dst[idx] = u;
    }
}

__global__ void seg_kernel(const int* __restrict__ batch) {
    int b = threadIdx.x;
    if (b <= BB) {
        int lo = 0, hi = NN;
        while (lo < hi) { int mid = (lo + hi) >> 1; if (batch[mid] < b) lo = mid + 1; else hi = mid; }
        g_seg[b] = lo;
    }
}
__global__ void init_copy(const float* __restrict__ h, const float* __restrict__ p) {
    int i = blockIdx.x * blockDim.x + threadIdx.x;
    if (i < NN*HH) g_h[0][i] = h[i];
    if (i < NN*3)  g_pos[0][i] = p[i];
}

// ---- standalone warp-per-node radius graph (final KI search only) ----
template<int KK, bool INTER>
__global__ __launch_bounds__(128) void neighbors_warp(int sel, const int* __restrict__ batch,
                                                      float cutoff2) {
    const int i = blockIdx.x * 4 + (threadIdx.x >> 5);
    const int lane = threadIdx.x & 31;
    if (i >= NN) return;
    nbr_search<KK>(i, lane, g_pos[sel], batch, cutoff2,
                   INTER ? g_iidx : g_idx, INTER ? g_icnt : g_cnt);
}

// ---- fused node(l)+pre(l+1) [+ optional neighbor search for the NEXT edge layer] ----
// mode: 0 = pre only, 1 = node+pre, 2 = node only
__global__ __launch_bounds__(256) void nodepre_kernel(
    int sel, int mode, int do_nbr, int psel, float cutoff2,
    const int* __restrict__ batch,
    const float* __restrict__ nw1, const float* __restrict__ nb1,
    const float* __restrict__ nw2, const float* __restrict__ nb2,
    const float* __restrict__ ew1, const float* __restrict__ eb1)
{
    int n0 = blockIdx.x * 8;
    int tid = threadIdx.x;
    int c = tid & 127, wg = tid >> 7;
    const float* h_in = g_h[sel];
    float* h_out = g_h[sel^1];
    __shared__ __align__(16) float s_hT[HH][12];
    __shared__ __align__(16) float s_aT[HH][12];

    #pragma unroll
    for (int e = 0; e < 4; e++) s_hT[c][wg*4 + e] = h_in[(n0 + wg*4 + e)*HH + c];
    if (mode != 0) {
        #pragma unroll
        for (int e = 0; e < 4; e++) s_aT[c][wg*4 + e] = g_agg[(n0 + wg*4 + e)*HH + c];
    }
    __syncthreads();

    if (mode != 0) {
        ull acc[2];
        ull b2 = pack2(nb1[c]);
        acc[0] = b2; acc[1] = b2;
        gemm_half<12>(acc, s_hT, nw1, c, wg);
        gemm_half<12>(acc, s_aT, nw1 + HH*HH, c, wg);
        __syncthreads();
        float2 f0 = unpack2(acc[0]), f1 = unpack2(acc[1]);
        s_aT[c][wg*4+0] = silu_f(f0.x); s_aT[c][wg*4+1] = silu_f(f0.y);
        s_aT[c][wg*4+2] = silu_f(f1.x); s_aT[c][wg*4+3] = silu_f(f1.y);
        __syncthreads();
        b2 = pack2(nb2[c]);
        acc[0] = b2; acc[1] = b2;
        gemm_half<12>(acc, s_aT, nw2, c, wg);
        f0 = unpack2(acc[0]); f1 = unpack2(acc[1]);
        float hv[4];
        hv[0] = s_hT[c][wg*4+0] + f0.x; hv[1] = s_hT[c][wg*4+1] + f0.y;
        hv[2] = s_hT[c][wg*4+2] + f1.x; hv[3] = s_hT[c][wg*4+3] + f1.y;
        #pragma unroll
        for (int e = 0; e < 4; e++) {
            h_out[(n0 + wg*4 + e)*HH + c] = hv[e];
            s_hT[c][wg*4 + e] = hv[e];
        }
        __syncthreads();
    }

    if (mode != 2) {
        ull acc[4];
        ull b2 = wg ? pack2(0.0f) : pack2(eb1[c]);
        #pragma unroll
        for (int q = 0; q < 4; q++) acc[q] = b2;
        gemm_t<2,12>(acc, s_hT, ew1 + wg*HH*HH, c, HH);
        float* outp = wg ? g_B : g_A;
        #pragma unroll
        for (int p = 0; p < 4; p++) {
            float2 f = unpack2(acc[p]);
            outp[(n0+2*p)*HH + c] = f.x; outp[(n0+2*p+1)*HH + c] = f.y;
        }
    }

    // neighbor search for the next (even) edge layer: warp w owns node n0+w.
    // pos[psel] is final here (written by the preceding edge launch / init).
    if (do_nbr) {
        int w = tid >> 5, lane = tid & 31;
        nbr_search<KM>(n0 + w, lane, g_pos[psel], batch, cutoff2, g_idx, g_cnt);
    }
}

// ---- edge kernel: 4 nodes/CTA, 6-term HMMA, dead-half skip (R14 state) ----
#define EDGE_DSM (128*SMP*4)

__global__ __launch_bounds__(256) void edge_mma_kernel(
    int sel, int layer,
    const float* __restrict__ ew1d, const float* __restrict__ eb2,
    const float* __restrict__ cb1,  const float* __restrict__ cw2)
{
    extern __shared__ float sM[];
    __shared__ int   sJ[128], sCnt[4];
    __shared__ float sMask[128], sD2[128], sRel[3*128];
    __shared__ float sWD[128], sEB2[128], sCB1[128], sCW2[128];
    __shared__ float sAgg[8][128];
    __shared__ float sCE[128];

    const int blk = blockIdx.x, tid = threadIdx.x;
    const int w = tid >> 5, lane = tid & 31, quad = lane >> 2, qt = lane & 3;
    const int nid = w & 3, half = w >> 2;
    const int r0 = (nid << 5) + (half << 4) + quad, r1 = r0 + 8;
    const float* p_in = g_pos[sel];
    float* p_out = g_pos[sel^1];

    if (tid < 4) sCnt[tid] = g_cnt[4*blk + tid];
    if (tid < 128) {
        int n = tid >> 5, e = tid & 31, i = 4*blk + n;
        int cnt = g_cnt[i];
        int j = (e < cnt) ? g_idx[i*KM + e] : i;
        sJ[tid] = j;
        sMask[tid] = (e < cnt) ? 1.0f : 0.0f;
        float rx = p_in[3*i] - p_in[3*j], ry = p_in[3*i+1] - p_in[3*j+1], rz = p_in[3*i+2] - p_in[3*j+2];
        sRel[tid] = rx; sRel[128+tid] = ry; sRel[256+tid] = rz;
        sD2[tid] = rx*rx + ry*ry + rz*rz;
        sWD[tid] = ew1d[tid]; sEB2[tid] = eb2[tid]; sCB1[tid] = cb1[tid]; sCW2[tid] = cw2[tid];
    }
    __syncthreads();

    const bool live = sCnt[nid] > half * 16;
    if (live) {
        const int iNode = 4*blk + nid;
        const int j0 = sJ[r0], j1 = sJ[r1];
        const float d20 = sD2[r0], d21 = sD2[r1];
        const float mk0 = sMask[r0], mk1 = sMask[r1];
        const float* gAi = g_A + (size_t)iNode*HH;
        const float* gB0 = g_B + (size_t)j0*HH;
        const float* gB1 = g_B + (size_t)j1*HH;

        const uint4* Wg = g_Wfrag + (size_t)layer*6*2048;
        const uint4* W1p0 = Wg + lane;
        const uint4* W1p1 = Wg + 2048 + lane;
        const uint4* W1p2 = Wg + 2*2048 + lane;
        const uint4* W2p0 = Wg + 3*2048 + lane;
        const uint4* W2p1 = Wg + 4*2048 + lane;
        const uint4* W2p2 = Wg + 5*2048 + lane;

        float acc[16][4];
        #pragma unroll
        for (int nt = 0; nt < 16; nt++) { acc[nt][0]=0.f; acc[nt][1]=0.f; acc[nt][2]=0.f; acc[nt][3]=0.f; }

        #pragma unroll
        for (int ks = 0; ks < 8; ks++) {
            int base = ks*16 + qt*2;
            float2 A0 = *reinterpret_cast<const float2*>(gAi + base);
            float2 A8 = *reinterpret_cast<const float2*>(gAi + base + 8);
            float2 B00 = *reinterpret_cast<const float2*>(gB0 + base);
            float2 B08 = *reinterpret_cast<const float2*>(gB0 + base + 8);
            float2 B10 = *reinterpret_cast<const float2*>(gB1 + base);
            float2 B18 = *reinterpret_cast<const float2*>(gB1 + base + 8);
            float2 w0 = *reinterpret_cast<const float2*>(sWD + base);
            float2 w8 = *reinterpret_cast<const float2*>(sWD + base + 8);
            uint32_t a0[4], a1[4], a2[4];
            split3x2(silu_f(fmaf(d20, w0.x, A0.x + B00.x)), silu_f(fmaf(d20, w0.y, A0.y + B00.y)), a0[0], a1[0], a2[0]);
            split3x2(silu_f(fmaf(d21, w0.x, A0.x + B10.x)), silu_f(fmaf(d21, w0.y, A0.y + B10.y)), a0[1], a1[1], a2[1]);
            split3x2(silu_f(fmaf(d20, w8.x, A8.x + B08.x)), silu_f(fmaf(d20, w8.y, A8.y + B08.y)), a0[2], a1[2], a2[2]);
            split3x2(silu_f(fmaf(d21, w8.x, A8.x + B18.x)), silu_f(fmaf(d21, w8.y, A8.y + B18.y)), a0[3], a1[3], a2[3]);
            gemm6(acc, a0, a1, a2, W1p0 + ks*256, W1p1 + ks*256, W1p2 + ks*256);
        }

        #pragma unroll
        for (int nt = 0; nt < 16; nt++) {
            int cc = nt*8 + qt*2;
            float m00 = silu_f(acc[nt][0] + sEB2[cc])   * mk0;
            float m01 = silu_f(acc[nt][1] + sEB2[cc+1]) * mk0;
            float m10 = silu_f(acc[nt][2] + sEB2[cc])   * mk1;
            float m11 = silu_f(acc[nt][3] + sEB2[cc+1]) * mk1;
            sM[r0*SMP + cc]   = m00; sM[r0*SMP + cc+1] = m01;
            sM[r1*SMP + cc]   = m10; sM[r1*SMP + cc+1] = m11;
            float s0 = m00 + m10, s1 = m01 + m11;
            #pragma unroll
            for (int off = 4; off <= 16; off <<= 1) {
                s0 += __shfl_xor_sync(0xffffffffu, s0, off);
                s1 += __shfl_xor_sync(0xffffffffu, s1, off);
            }
            if (quad == 0) { sAgg[w][cc] = s0; sAgg[w][cc+1] = s1; }
            acc[nt][0] = 0.f; acc[nt][1] = 0.f; acc[nt][2] = 0.f; acc[nt][3] = 0.f;
        }

        gemm_sT(acc, sM, r0, r1, qt, W2p0, W2p1, W2p2);

        float p0 = 0.f, p1 = 0.f;
        #pragma unroll
        for (int nt = 0; nt < 16; nt++) {
            int cc = nt*8 + qt*2;
            p0 += silu_f(acc[nt][0] + sCB1[cc])*sCW2[cc] + silu_f(acc[nt][1] + sCB1[cc+1])*sCW2[cc+1];
            p1 += silu_f(acc[nt][2] + sCB1[cc])*sCW2[cc] + silu_f(acc[nt][3] + sCB1[cc+1])*sCW2[cc+1];
        }
        p0 += __shfl_xor_sync(0xffffffffu, p0, 1); p0 += __shfl_xor_sync(0xffffffffu, p0, 2);
        p1 += __shfl_xor_sync(0xffffffffu, p1, 1); p1 += __shfl_xor_sync(0xffffffffu, p1, 2);
        if (qt == 0) { sCE[r0] = p0; sCE[r1] = p1; }
    } else {
        for (int x = lane; x < 128; x += 32) sAgg[w][x] = 0.f;
        if (qt == 0) { sCE[r0] = 0.f; sCE[r1] = 0.f; }
    }
    __syncthreads();

    #pragma unroll
    for (int rep = 0; rep < 2; rep++) {
        int idx = tid + 256*rep;
        int n = idx >> 7, c = idx & 127;
        g_agg[(4*blk + n)*HH + c] = sAgg[n][c] + sAgg[n+4][c];
    }

    if (w < 4) {
        int r = 32*w + lane, i = 4*blk + w;
        float ce = sCE[r], mk = sMask[r];
        float fx = sRel[r]*ce*mk, fy = sRel[128+r]*ce*mk, fz = sRel[256+r]*ce*mk;
        #pragma unroll
        for (int o = 16; o > 0; o >>= 1) {
            fx += __shfl_down_sync(0xffffffffu, fx, o);
            fy += __shfl_down_sync(0xffffffffu, fy, o);
            fz += __shfl_down_sync(0xffffffffu, fz, o);
        }
        if (lane == 0) {
            float cnt = fmaxf((float)g_cnt[i], 1.0f);
            p_out[3*i+0] = p_in[3*i+0] + fx / cnt;
            p_out[3*i+1] = p_in[3*i+1] + fy / cnt;
            p_out[3*i+2] = p_in[3*i+2] + fz / cnt;
        }
    }
}

// ---- final readout (TILE=32) ----
__global__ __launch_bounds__(HH) void final_tile_kernel(
    const float* __restrict__ fw1, const float* __restrict__ fb1,
    const float* __restrict__ fw2, const float* __restrict__ fb2,
    const float* __restrict__ ccw1, const float* __restrict__ ccb1,
    const float* __restrict__ ccw2, const float* __restrict__ ccb2,
    const float* __restrict__ sw,  const float* __restrict__ sb,
    const float* __restrict__ iw,
    float* __restrict__ out)
{
    int n0 = blockIdx.x * 32, c = threadIdx.x;
    const float* h = g_h[0];
    const float* p = g_pos[0];
    __shared__ __align__(16) float s_hT[HH][36];
    __shared__ __align__(16) float s_tT[HH][36];

    #pragma unroll
    for (int e = 0; e < 32; e++) {
        float v = h[(n0+e)*HH + c];
        s_hT[c][e] = v;
        out[OFF_H + (n0+e)*HH + c] = v;
    }
    if (c < 3)
        for (int e = 0; e < 32; e++) out[OFF_POS + (n0+e)*3 + c] = p[(n0+e)*3 + c];
    __syncthreads();

    ull acc[16];
    ull b2 = pack2(fb1[c]);
    #pragma unroll
    for (int q = 0; q < 16; q++) acc[q] = b2;
    gemm_t<8,36>(acc, s_hT, fw1, c, HH);
    #pragma unroll
    for (int p2 = 0; p2 < 16; p2++) {
        float2 f = unpack2(acc[p2]);
        s_tT[c][2*p2] = tanhf(f.x); s_tT[c][2*p2+1] = tanhf(f.y);
    }
    __syncthreads();
    if (c < 96) {
        int e = c / 3, t = c % 3;
        float s = 0.0f;
        #pragma unroll 8
        for (int k = 0; k < HH; k++) s += s_tT[k][e] * fw2[k*3 + t];
        out[OFF_F + (n0+e)*3 + t] = s + fb2[t];
    }
    if (c < 32) {
        float s = 0.0f;
        #pragma unroll 8
        for (int k = 0; k < HH; k++) s += s_hT[k][c] * sw[k];
        out[OFF_ST + n0 + c] = s + sb[0];
        #pragma unroll
        for (int t = 0; t < 3; t++) {
            float da = 0.0f, db = 0.0f;
            const float* iwt = iw + t*258;
            #pragma unroll 8
            for (int k = 0; k < HH; k++) {
                float hv = s_hT[k][c];
                da += hv * iwt[k]; db += hv * iwt[128 + k];
            }
            g_dots[t][n0 + c] = da; g_dots[3+t][n0 + c] = db;
        }
    }
    __syncthreads();

    b2 = pack2(ccb1[c]);
    #pragma unroll
    for (int q = 0; q < 16; q++) acc[q] = b2;
    gemm_t<8,36>(acc, s_hT, ccw1, c, HH);
    #pragma unroll
    for (int p2 = 0; p2 < 16; p2++) {
        float2 f = unpack2(acc[p2]);
        s_tT[c][2*p2] = fmaxf(f.x, 0.0f); s_tT[c][2*p2+1] = fmaxf(f.y, 0.0f);
    }
    __syncthreads();
    if (c < 64) {
        ull bb = pack2(ccb2[c]);
        #pragma unroll
        for (int q = 0; q < 16; q++) acc[q] = bb;
        #pragma unroll 4
        for (int k = 0; k < HH; k++) {
            ull w2 = pack2(ccw2[k*64 + c]);
            const ulonglong2* r = reinterpret_cast<const ulonglong2*>(s_tT[k]);
            #pragma unroll
            for (int q = 0; q < 8; q++) {
                ulonglong2 v = r[q];
                ffma2(acc[2*q], v.x, w2); ffma2(acc[2*q+1], v.y, w2);
            }
        }
        #pragma unroll
        for (int p2 = 0; p2 < 16; p2++) {
            float2 f = unpack2(acc[p2]);
            out[OFF_CONF + (n0+2*p2)*64 + c]   = f.x;
            out[OFF_CONF + (n0+2*p2+1)*64 + c] = f.y;
        }
    }
}

__global__ void scores_kernel(const float* __restrict__ iw, const float* __restrict__ ib,
                              float* __restrict__ out) {
    int idx = blockIdx.x * blockDim.x + threadIdx.x;
    if (idx >= NN*KI) return;
    int i = idx / KI, e = idx % KI;
    const float* p = g_pos[0];
    int cnt = g_icnt[i];
    int j = g_iidx[i*KI + e];
    float mask = (e < cnt) ? 1.0f : 0.0f;
    float dx = p[3*i]-p[3*j], dy = p[3*i+1]-p[3*j+1], dz = p[3*i+2]-p[3*j+2];
    float dist = sqrtf(dx*dx + dy*dy + dz*dz + 1e-12f);
    #pragma unroll
    for (int t = 0; t < 3; t++) {
        const float* iwt = iw + t*258;
        float x = g_dots[t][i] + g_dots[3+t][j] + dist*iwt[256] + (dist/10.0f)*iwt[257] + ib[t];
        out[OFF_S + t*(NN*KI) + i*KI + e] = __fdividef(1.0f, 1.0f + __expf(-x)) * mask;
    }
}

extern "C" void kernel_launch(void* const* d_in, const int* in_sizes, int n_in,
                              void* d_out, int out_size)
{
    const float* h     = (const float*)d_in[0];
    const float* pos   = (const float*)d_in[1];
    const int*   batch = (const int*)  d_in[2];
    const float* ew1   = (const float*)d_in[3];
    const float* eb1   = (const float*)d_in[4];
    const float* ew2   = (const float*)d_in[5];
    const float* eb2   = (const float*)d_in[6];
    const float* cw1   = (const float*)d_in[7];
    const float* cb1   = (const float*)d_in[8];
    const float* cw2   = (const float*)d_in[9];
    const float* nw1   = (const float*)d_in[10];
    const float* nb1   = (const float*)d_in[11];
    const float* nw2   = (const float*)d_in[12];
    const float* nb2   = (const float*)d_in[13];
    const float* fw1   = (const float*)d_in[14];
    const float* fb1   = (const float*)d_in[15];
    const float* fw2   = (const float*)d_in[16];
    const float* fb2   = (const float*)d_in[17];
    const float* iw    = (const float*)d_in[18];
    const float* ib    = (const float*)d_in[19];
    const float* ccw1  = (const float*)d_in[20];
    const float* ccb1  = (const float*)d_in[21];
    const float* ccw2  = (const float*)d_in[22];
    const float* ccb2  = (const float*)d_in[23];
    const float* sw    = (const float*)d_in[24];
    const float* sb    = (const float*)d_in[25];
    float* out = (float*)d_out;

    cudaFuncSetAttribute(edge_mma_kernel, cudaFuncAttributeMaxDynamicSharedMemorySize, EDGE_DSM);

    seg_kernel<<<1, 64>>>(batch);
    init_copy<<<(NN*HH + 255)/256, 256>>>(h, pos);
    wprep_kernel<<<36, 256>>>(ew2, cw1);

    const float cut2[3] = {9.0f, 36.0f, 100.0f};
    int sel = 0;
    // layer 0 pre + layer-0 neighbor search on pos[0]
    nodepre_kernel<<<NN/8, 256>>>(0, 0, 1, 0, cut2[0], batch,
                                  nw1, nb1, nw2, nb2, ew1, eb1);
    for (int l = 0; l < 6; l++) {
        edge_mma_kernel<<<NN/4, 256, EDGE_DSM>>>(sel, l, ew1 + l*257*HH + 256*HH,
                                                 eb2 + l*HH, cb1 + l*HH, cw2 + l*HH);
        int mode = (l < 5) ? 1 : 2;
        int lp = (l < 5) ? l + 1 : 0;
        // fuse neighbor search for layer l+1 (if even) using pos after edge(l) = pos[sel^1]
        int do_nbr = (l < 5 && ((l + 1) & 1) == 0) ? 1 : 0;
        nodepre_kernel<<<NN/8, 256>>>(sel, mode, do_nbr, sel ^ 1,
                                      (l + 1 < 6) ? cut2[(l+1)/2] : 0.0f, batch,
                                      nw1 + l*256*HH, nb1 + l*HH,
                                      nw2 + l*HH*HH,  nb2 + l*HH,
                                      ew1 + lp*257*HH, eb1 + lp*HH);
        sel ^= 1;
    }
    neighbors_warp<KI, true><<<NN/4, 128>>>(0, batch, 100.0f);
    final_tile_kernel<<<NN/32, HH>>>(fw1, fb1, fw2, fb2,
                                     ccw1, ccb1, ccw2, ccb2, sw, sb, iw, out);
    scores_kernel<<<(NN*KI + 255)/256, 256>>>(iw, ib, out);
}

// round 17
// speedup vs baseline: 1.0481x; 1.0009x over previous
#include <cuda_runtime.h>
#include <cuda_bf16.h>
#include <cstdint>
#include <math.h>

#define NN 4096
#define HH 128
#define KM 32
#define KI 20
#define BB 32
#define SMP 132
#define NL 12

#define OFF_H    0
#define OFF_POS  (NN*HH)
#define OFF_F    (OFF_POS + NN*3)
#define OFF_S    (OFF_F + NN*3)
#define OFF_CONF (OFF_S + 3*NN*KI)
#define OFF_ST   (OFF_CONF + NN*64)

typedef unsigned long long ull;

__device__ float g_h[2][NN*HH];
__device__ float g_pos[2][NN*3];
__device__ float g_A[NN*HH];
__device__ float g_B[NN*HH];
__device__ float g_agg[NN*HH];
__device__ float g_dots[6][NN];
__device__ int   g_idx[NN*KM];
__device__ int   g_cnt[NN];
__device__ int   g_iidx[NN*KI];
__device__ int   g_icnt[NN];
__device__ int   g_seg[BB+1];
// fragment-packed bf16 weights, uint4-paired n-tiles (mats: ew2, cw1)
__device__ __align__(16) uint4 g_Wfrag[36*2048];

__device__ __forceinline__ float silu_f(float x) {
    return __fdividef(x, 1.0f + __expf(-x));
}

// ---- packed fp32x2 scalar GEMM helpers ----
__device__ __forceinline__ ull pack2(float x) {
    ull r; asm("mov.b64 %0, {%1, %1};" : "=l"(r) : "r"(__float_as_uint(x))); return r;
}
__device__ __forceinline__ void ffma2(ull& a, ull v, ull w) {
    asm("fma.rn.f32x2 %0, %1, %2, %0;" : "+l"(a) : "l"(v), "l"(w));
}
__device__ __forceinline__ float2 unpack2(ull a) {
    unsigned lo, hi; asm("mov.b64 {%0, %1}, %2;" : "=r"(lo), "=r"(hi) : "l"(a));
    return make_float2(__uint_as_float(lo), __uint_as_float(hi));
}
template<int NE2, int TP>
__device__ __forceinline__ void gemm_t(ull* acc, const float (*T)[TP],
                                       const float* __restrict__ W, int c, int kk) {
    #pragma unroll 4
    for (int k = 0; k < kk; k++) {
        ull w2 = pack2(W[k*HH + c]);
        const ulonglong2* r = reinterpret_cast<const ulonglong2*>(T[k]);
        #pragma unroll
        for (int q = 0; q < NE2; q++) {
            ulonglong2 v = r[q];
            ffma2(acc[2*q], v.x, w2); ffma2(acc[2*q+1], v.y, w2);
        }
    }
}
// half-tile: 4 node-columns at ulonglong2 offset eo (bit-identical q=eo slice)
template<int TP>
__device__ __forceinline__ void gemm_half(ull* acc, const float (*T)[TP],
                                          const float* __restrict__ W, int c, int eo) {
    #pragma unroll 4
    for (int k = 0; k < HH; k++) {
        ull w2 = pack2(W[k*HH + c]);
        const ulonglong2* r = reinterpret_cast<const ulonglong2*>(T[k]) + eo;
        ulonglong2 v = r[0];
        ffma2(acc[0], v.x, w2); ffma2(acc[1], v.y, w2);
    }
}

// ---- mma.sync helpers ----
__device__ __forceinline__ void mma_bf16(float* d, const uint32_t* a, uint32_t bx, uint32_t by) {
    asm volatile("mma.sync.aligned.m16n8k16.row.col.f32.bf16.bf16.f32 "
        "{%0,%1,%2,%3}, {%4,%5,%6,%7}, {%8,%9}, {%0,%1,%2,%3};"
        : "+f"(d[0]), "+f"(d[1]), "+f"(d[2]), "+f"(d[3])
        : "r"(a[0]), "r"(a[1]), "r"(a[2]), "r"(a[3]), "r"(bx), "r"(by));
}
__device__ __forceinline__ void split3x2(float x, float y,
                                         uint32_t& u0, uint32_t& u1, uint32_t& u2) {
    __nv_bfloat162 v0 = __floats2bfloat162_rn(x, y);
    float rx = x - __bfloat162float(v0.x), ry = y - __bfloat162float(v0.y);
    __nv_bfloat162 v1 = __floats2bfloat162_rn(rx, ry);
    rx -= __bfloat162float(v1.x); ry -= __bfloat162float(v1.y);
    __nv_bfloat162 v2 = __floats2bfloat162_rn(rx, ry);
    u0 = *reinterpret_cast<uint32_t*>(&v0);
    u1 = *reinterpret_cast<uint32_t*>(&v1);
    u2 = *reinterpret_cast<uint32_t*>(&v2);
}
__device__ __forceinline__ __nv_bfloat16 wpart3(float w, int part) {
    __nv_bfloat16 p0 = __float2bfloat16(w);
    if (part == 0) return p0;
    float r = w - __bfloat162float(p0);
    __nv_bfloat16 p1 = __float2bfloat16(r);
    if (part == 1) return p1;
    return __float2bfloat16(r - __bfloat162float(p1));
}
__device__ __forceinline__ void term16(float (*acc)[4], const uint32_t* a,
                                       const uint4* __restrict__ p) {
    #pragma unroll
    for (int np = 0; np < 8; np++) {
        uint4 b = __ldg(p + np*32);
        mma_bf16(acc[2*np],   a, b.x, b.y);
        mma_bf16(acc[2*np+1], a, b.z, b.w);
    }
}
__device__ __forceinline__ void gemm6(float (*acc)[4],
                                      const uint32_t* a0, const uint32_t* a1, const uint32_t* a2,
                                      const uint4* __restrict__ p0, const uint4* __restrict__ p1,
                                      const uint4* __restrict__ p2) {
    term16(acc, a0, p0);
    term16(acc, a0, p1);
    term16(acc, a1, p0);
    term16(acc, a0, p2);
    term16(acc, a1, p1);
    term16(acc, a2, p0);
}
__device__ __forceinline__ void gemm_sT(float (*acc)[4], const float* sT,
                                        int r0, int r1, int qt,
                                        const uint4* p0, const uint4* p1, const uint4* p2) {
    #pragma unroll
    for (int ks = 0; ks < 8; ks++) {
        int k0 = ks*16 + qt*2;
        float2 x00 = *reinterpret_cast<const float2*>(sT + r0*SMP + k0);
        float2 x10 = *reinterpret_cast<const float2*>(sT + r1*SMP + k0);
        float2 x08 = *reinterpret_cast<const float2*>(sT + r0*SMP + k0 + 8);
        float2 x18 = *reinterpret_cast<const float2*>(sT + r1*SMP + k0 + 8);
        uint32_t a0[4], a1[4], a2[4];
        split3x2(x00.x, x00.y, a0[0], a1[0], a2[0]);
        split3x2(x10.x, x10.y, a0[1], a1[1], a2[1]);
        split3x2(x08.x, x08.y, a0[2], a1[2], a2[2]);
        split3x2(x18.x, x18.y, a0[3], a1[3], a2[3]);
        gemm6(acc, a0, a1, a2, p0 + ks*256, p1 + ks*256, p2 + ks*256);
    }
}

// ---- warp-local neighbor search for node i ----
template<int KK>
__device__ __forceinline__ void nbr_search(int i, int lane, const float* __restrict__ p,
                                           const int* __restrict__ batch, float cutoff2,
                                           int* __restrict__ oi, int* __restrict__ oc) {
    int b = batch[i];
    int s0 = g_seg[b], s1 = g_seg[b+1];
    float px = p[3*i], py = p[3*i+1], pz = p[3*i+2];
    const ull KMAX = ~0ull;
    ull keys[NL];
    #pragma unroll
    for (int q = 0; q < NL; q++) {
        int j = s0 + lane + q*32;
        ull key = KMAX;
        if (j < s1 && j != i) {
            float dx = px - p[3*j], dy = py - p[3*j+1], dz = pz - p[3*j+2];
            float d2 = dx*dx + dy*dy + dz*dz;
            if (d2 <= cutoff2)
                key = ((ull)__float_as_uint(d2) << 32) | (unsigned)j;
        }
        keys[q] = key;
    }
    ull mymin = KMAX;
    #pragma unroll
    for (int q = 0; q < NL; q++) mymin = min(mymin, keys[q]);
    int myout = i;
    int cnt = 0;
    for (int e = 0; e < KK; e++) {
        ull mn = mymin;
        #pragma unroll
        for (int o = 16; o > 0; o >>= 1) {
            ull ot = __shfl_xor_sync(0xffffffffu, mn, o);
            mn = min(mn, ot);
        }
        if (mn == KMAX) break;
        if (lane == e) myout = (int)(unsigned)(mn & 0xffffffffu);
        cnt++;
        if (mymin == mn) {
            #pragma unroll
            for (int q = 0; q < NL; q++) if (keys[q] == mn) keys[q] = KMAX;
            mymin = KMAX;
            #pragma unroll
            for (int q = 0; q < NL; q++) mymin = min(mymin, keys[q]);
        }
    }
    if (lane < KK) oi[i*KK + lane] = myout;
    if (lane == 0) oc[i] = cnt;
}

// ---- fused setup: blocks [0,2048) init_copy, [2048,2084) wprep, 2084 seg ----
__global__ void setup_kernel(const float* __restrict__ h, const float* __restrict__ p,
                             const int* __restrict__ batch,
                             const float* __restrict__ ew2, const float* __restrict__ cw1) {
    int blk = blockIdx.x;
    if (blk < 2048) {
        int i = blk * 256 + threadIdx.x;
        g_h[0][i] = h[i];
        if (i < NN*3) g_pos[0][i] = p[i];
        return;
    }
    if (blk < 2084) {
        int b = blk - 2048;            // (l*2+mat)*3+part
        int part = b % 3, mat = (b / 3) % 2, l = b / 6;
        const float* W = (mat ? cw1 : ew2) + l * HH * HH;
        uint4* dst = g_Wfrag + (size_t)b * 2048;
        for (int idx = threadIdx.x; idx < 2048; idx += blockDim.x) {
            int lane = idx & 31, np = (idx >> 5) & 7, ks = idx >> 8;
            int quad = lane >> 2, qt = lane & 3;
            int k0 = ks*16 + qt*2;
            uint4 u;
            #pragma unroll
            for (int half = 0; half < 2; half++) {
                int n = (2*np + half)*8 + quad;
                __nv_bfloat162 v0, v1;
                v0.x = wpart3(W[k0*HH + n], part);     v0.y = wpart3(W[(k0+1)*HH + n], part);
                v1.x = wpart3(W[(k0+8)*HH + n], part); v1.y = wpart3(W[(k0+9)*HH + n], part);
                if (half == 0) { u.x = *reinterpret_cast<uint32_t*>(&v0); u.y = *reinterpret_cast<uint32_t*>(&v1); }
                else           { u.z = *reinterpret_cast<uint32_t*>(&v0); u.w = *reinterpret_cast<uint32_t*>(&v1); }
            }
            dst[idx] = u;
        }
        return;
    }
    int b = threadIdx.x;
    if (b <= BB) {
        int lo = 0, hi = NN;
        while (lo < hi) { int mid = (lo + hi) >> 1; if (batch[mid] < b) lo = mid + 1; else hi = mid; }
        g_seg[b] = lo;
    }
}

// ---- fused node(l)+pre(l+1) [+ optional neighbor search] ----
// mode: 0 = pre only, 1 = node+pre, 2 = node only
// nbrk: 0 = none, 1 = KM search -> g_idx/g_cnt, 2 = KI search -> g_iidx/g_icnt
__global__ __launch_bounds__(256) void nodepre_kernel(
    int sel, int mode, int nbrk, int psel, float cutoff2,
    const int* __restrict__ batch,
    const float* __restrict__ nw1, const float* __restrict__ nb1,
    const float* __restrict__ nw2, const float* __restrict__ nb2,
    const float* __restrict__ ew1, const float* __restrict__ eb1)
{
    int n0 = blockIdx.x * 8;
    int tid = threadIdx.x;
    int c = tid & 127, wg = tid >> 7;
    const float* h_in = g_h[sel];
    float* h_out = g_h[sel^1];
    __shared__ __align__(16) float s_hT[HH][12];
    __shared__ __align__(16) float s_aT[HH][12];

    #pragma unroll
    for (int e = 0; e < 4; e++) s_hT[c][wg*4 + e] = h_in[(n0 + wg*4 + e)*HH + c];
    if (mode != 0) {
        #pragma unroll
        for (int e = 0; e < 4; e++) s_aT[c][wg*4 + e] = g_agg[(n0 + wg*4 + e)*HH + c];
    }
    __syncthreads();

    if (mode != 0) {
        ull acc[2];
        ull b2 = pack2(nb1[c]);
        acc[0] = b2; acc[1] = b2;
        gemm_half<12>(acc, s_hT, nw1, c, wg);
        gemm_half<12>(acc, s_aT, nw1 + HH*HH, c, wg);
        __syncthreads();
        float2 f0 = unpack2(acc[0]), f1 = unpack2(acc[1]);
        s_aT[c][wg*4+0] = silu_f(f0.x); s_aT[c][wg*4+1] = silu_f(f0.y);
        s_aT[c][wg*4+2] = silu_f(f1.x); s_aT[c][wg*4+3] = silu_f(f1.y);
        __syncthreads();
        b2 = pack2(nb2[c]);
        acc[0] = b2; acc[1] = b2;
        gemm_half<12>(acc, s_aT, nw2, c, wg);
        f0 = unpack2(acc[0]); f1 = unpack2(acc[1]);
        float hv[4];
        hv[0] = s_hT[c][wg*4+0] + f0.x; hv[1] = s_hT[c][wg*4+1] + f0.y;
        hv[2] = s_hT[c][wg*4+2] + f1.x; hv[3] = s_hT[c][wg*4+3] + f1.y;
        #pragma unroll
        for (int e = 0; e < 4; e++) {
            h_out[(n0 + wg*4 + e)*HH + c] = hv[e];
            s_hT[c][wg*4 + e] = hv[e];
        }
        __syncthreads();
    }

    if (mode != 2) {
        ull acc[4];
        ull b2 = wg ? pack2(0.0f) : pack2(eb1[c]);
        #pragma unroll
        for (int q = 0; q < 4; q++) acc[q] = b2;
        gemm_t<2,12>(acc, s_hT, ew1 + wg*HH*HH, c, HH);
        float* outp = wg ? g_B : g_A;
        #pragma unroll
        for (int p = 0; p < 4; p++) {
            float2 f = unpack2(acc[p]);
            outp[(n0+2*p)*HH + c] = f.x; outp[(n0+2*p+1)*HH + c] = f.y;
        }
    }

    // fused neighbor search (warp w owns node n0+w; pos[psel] is final here)
    if (nbrk == 1) {
        int w = tid >> 5, lane = tid & 31;
        nbr_search<KM>(n0 + w, lane, g_pos[psel], batch, cutoff2, g_idx, g_cnt);
    } else if (nbrk == 2) {
        int w = tid >> 5, lane = tid & 31;
        nbr_search<KI>(n0 + w, lane, g_pos[psel], batch, cutoff2, g_iidx, g_icnt);
    }
}

// ---- edge kernel: 4 nodes/CTA, 6-term HMMA, dead-half skip (R14 state) ----
#define EDGE_DSM (128*SMP*4)

__global__ __launch_bounds__(256) void edge_mma_kernel(
    int sel, int layer,
    const float* __restrict__ ew1d, const float* __restrict__ eb2,
    const float* __restrict__ cb1,  const float* __restrict__ cw2)
{
    extern __shared__ float sM[];
    __shared__ int   sJ[128], sCnt[4];
    __shared__ float sMask[128], sD2[128], sRel[3*128];
    __shared__ float sWD[128], sEB2[128], sCB1[128], sCW2[128];
    __shared__ float sAgg[8][128];
    __shared__ float sCE[128];

    const int blk = blockIdx.x, tid = threadIdx.x;
    const int w = tid >> 5, lane = tid & 31, quad = lane >> 2, qt = lane & 3;
    const int nid = w & 3, half = w >> 2;
    const int r0 = (nid << 5) + (half << 4) + quad, r1 = r0 + 8;
    const float* p_in = g_pos[sel];
    float* p_out = g_pos[sel^1];

    if (tid < 4) sCnt[tid] = g_cnt[4*blk + tid];
    if (tid < 128) {
        int n = tid >> 5, e = tid & 31, i = 4*blk + n;
        int cnt = g_cnt[i];
        int j = (e < cnt) ? g_idx[i*KM + e] : i;
        sJ[tid] = j;
        sMask[tid] = (e < cnt) ? 1.0f : 0.0f;
        float rx = p_in[3*i] - p_in[3*j], ry = p_in[3*i+1] - p_in[3*j+1], rz = p_in[3*i+2] - p_in[3*j+2];
        sRel[tid] = rx; sRel[128+tid] = ry; sRel[256+tid] = rz;
        sD2[tid] = rx*rx + ry*ry + rz*rz;
        sWD[tid] = ew1d[tid]; sEB2[tid] = eb2[tid]; sCB1[tid] = cb1[tid]; sCW2[tid] = cw2[tid];
    }
    __syncthreads();

    const bool live = sCnt[nid] > half * 16;
    if (live) {
        const int iNode = 4*blk + nid;
        const int j0 = sJ[r0], j1 = sJ[r1];
        const float d20 = sD2[r0], d21 = sD2[r1];
        const float mk0 = sMask[r0], mk1 = sMask[r1];
        const float* gAi = g_A + (size_t)iNode*HH;
        const float* gB0 = g_B + (size_t)j0*HH;
        const float* gB1 = g_B + (size_t)j1*HH;

        const uint4* Wg = g_Wfrag + (size_t)layer*6*2048;
        const uint4* W1p0 = Wg + lane;
        const uint4* W1p1 = Wg + 2048 + lane;
        const uint4* W1p2 = Wg + 2*2048 + lane;
        const uint4* W2p0 = Wg + 3*2048 + lane;
        const uint4* W2p1 = Wg + 4*2048 + lane;
        const uint4* W2p2 = Wg + 5*2048 + lane;

        float acc[16][4];
        #pragma unroll
        for (int nt = 0; nt < 16; nt++) { acc[nt][0]=0.f; acc[nt][1]=0.f; acc[nt][2]=0.f; acc[nt][3]=0.f; }

        #pragma unroll
        for (int ks = 0; ks < 8; ks++) {
            int base = ks*16 + qt*2;
            float2 A0 = *reinterpret_cast<const float2*>(gAi + base);
            float2 A8 = *reinterpret_cast<const float2*>(gAi + base + 8);
            float2 B00 = *reinterpret_cast<const float2*>(gB0 + base);
            float2 B08 = *reinterpret_cast<const float2*>(gB0 + base + 8);
            float2 B10 = *reinterpret_cast<const float2*>(gB1 + base);
            float2 B18 = *reinterpret_cast<const float2*>(gB1 + base + 8);
            float2 w0 = *reinterpret_cast<const float2*>(sWD + base);
            float2 w8 = *reinterpret_cast<const float2*>(sWD + base + 8);
            uint32_t a0[4], a1[4], a2[4];
            split3x2(silu_f(fmaf(d20, w0.x, A0.x + B00.x)), silu_f(fmaf(d20, w0.y, A0.y + B00.y)), a0[0], a1[0], a2[0]);
            split3x2(silu_f(fmaf(d21, w0.x, A0.x + B10.x)), silu_f(fmaf(d21, w0.y, A0.y + B10.y)), a0[1], a1[1], a2[1]);
            split3x2(silu_f(fmaf(d20, w8.x, A8.x + B08.x)), silu_f(fmaf(d20, w8.y, A8.y + B08.y)), a0[2], a1[2], a2[2]);
            split3x2(silu_f(fmaf(d21, w8.x, A8.x + B18.x)), silu_f(fmaf(d21, w8.y, A8.y + B18.y)), a0[3], a1[3], a2[3]);
            gemm6(acc, a0, a1, a2, W1p0 + ks*256, W1p1 + ks*256, W1p2 + ks*256);
        }

        #pragma unroll
        for (int nt = 0; nt < 16; nt++) {
            int cc = nt*8 + qt*2;
            float m00 = silu_f(acc[nt][0] + sEB2[cc])   * mk0;
            float m01 = silu_f(acc[nt][1] + sEB2[cc+1]) * mk0;
            float m10 = silu_f(acc[nt][2] + sEB2[cc])   * mk1;
            float m11 = silu_f(acc[nt][3] + sEB2[cc+1]) * mk1;
            sM[r0*SMP + cc]   = m00; sM[r0*SMP + cc+1] = m01;
            sM[r1*SMP + cc]   = m10; sM[r1*SMP + cc+1] = m11;
            float s0 = m00 + m10, s1 = m01 + m11;
            #pragma unroll
            for (int off = 4; off <= 16; off <<= 1) {
                s0 += __shfl_xor_sync(0xffffffffu, s0, off);
                s1 += __shfl_xor_sync(0xffffffffu, s1, off);
            }
            if (quad == 0) { sAgg[w][cc] = s0; sAgg[w][cc+1] = s1; }
            acc[nt][0] = 0.f; acc[nt][1] = 0.f; acc[nt][2] = 0.f; acc[nt][3] = 0.f;
        }

        gemm_sT(acc, sM, r0, r1, qt, W2p0, W2p1, W2p2);

        float p0 = 0.f, p1 = 0.f;
        #pragma unroll
        for (int nt = 0; nt < 16; nt++) {
            int cc = nt*8 + qt*2;
            p0 += silu_f(acc[nt][0] + sCB1[cc])*sCW2[cc] + silu_f(acc[nt][1] + sCB1[cc+1])*sCW2[cc+1];
            p1 += silu_f(acc[nt][2] + sCB1[cc])*sCW2[cc] + silu_f(acc[nt][3] + sCB1[cc+1])*sCW2[cc+1];
        }
        p0 += __shfl_xor_sync(0xffffffffu, p0, 1); p0 += __shfl_xor_sync(0xffffffffu, p0, 2);
        p1 += __shfl_xor_sync(0xffffffffu, p1, 1); p1 += __shfl_xor_sync(0xffffffffu, p1, 2);
        if (qt == 0) { sCE[r0] = p0; sCE[r1] = p1; }
    } else {
        for (int x = lane; x < 128; x += 32) sAgg[w][x] = 0.f;
        if (qt == 0) { sCE[r0] = 0.f; sCE[r1] = 0.f; }
    }
    __syncthreads();

    #pragma unroll
    for (int rep = 0; rep < 2; rep++) {
        int idx = tid + 256*rep;
        int n = idx >> 7, c = idx & 127;
        g_agg[(4*blk + n)*HH + c] = sAgg[n][c] + sAgg[n+4][c];
    }

    if (w < 4) {
        int r = 32*w + lane, i = 4*blk + w;
        float ce = sCE[r], mk = sMask[r];
        float fx = sRel[r]*ce*mk, fy = sRel[128+r]*ce*mk, fz = sRel[256+r]*ce*mk;
        #pragma unroll
        for (int o = 16; o > 0; o >>= 1) {
            fx += __shfl_down_sync(0xffffffffu, fx, o);
            fy += __shfl_down_sync(0xffffffffu, fy, o);
            fz += __shfl_down_sync(0xffffffffu, fz, o);
        }
        if (lane == 0) {
            float cnt = fmaxf((float)g_cnt[i], 1.0f);
            p_out[3*i+0] = p_in[3*i+0] + fx / cnt;
            p_out[3*i+1] = p_in[3*i+1] + fy / cnt;
            p_out[3*i+2] = p_in[3*i+2] + fz / cnt;
        }
    }
}

// ---- final readout (TILE=32) ----
__global__ __launch_bounds__(HH) void final_tile_kernel(
    const float* __restrict__ fw1, const float* __restrict__ fb1,
    const float* __restrict__ fw2, const float* __restrict__ fb2,
    const float* __restrict__ ccw1, const float* __restrict__ ccb1,
    const float* __restrict__ ccw2, const float* __restrict__ ccb2,
    const float* __restrict__ sw,  const float* __restrict__ sb,
    const float* __restrict__ iw,
    float* __restrict__ out)
{
    int n0 = blockIdx.x * 32, c = threadIdx.x;
    const float* h = g_h[0];
    const float* p = g_pos[0];
    __shared__ __align__(16) float s_hT[HH][36];
    __shared__ __align__(16) float s_tT[HH][36];

    #pragma unroll
    for (int e = 0; e < 32; e++) {
        float v = h[(n0+e)*HH + c];
        s_hT[c][e] = v;
        out[OFF_H + (n0+e)*HH + c] = v;
    }
    if (c < 3)
        for (int e = 0; e < 32; e++) out[OFF_POS + (n0+e)*3 + c] = p[(n0+e)*3 + c];
    __syncthreads();

    ull acc[16];
    ull b2 = pack2(fb1[c]);
    #pragma unroll
    for (int q = 0; q < 16; q++) acc[q] = b2;
    gemm_t<8,36>(acc, s_hT, fw1, c, HH);
    #pragma unroll
    for (int p2 = 0; p2 < 16; p2++) {
        float2 f = unpack2(acc[p2]);
        s_tT[c][2*p2] = tanhf(f.x); s_tT[c][2*p2+1] = tanhf(f.y);
    }
    __syncthreads();
    if (c < 96) {
        int e = c / 3, t = c % 3;
        float s = 0.0f;
        #pragma unroll 8
        for (int k = 0; k < HH; k++) s += s_tT[k][e] * fw2[k*3 + t];
        out[OFF_F + (n0+e)*3 + t] = s + fb2[t];
    }
    if (c < 32) {
        float s = 0.0f;
        #pragma unroll 8
        for (int k = 0; k < HH; k++) s += s_hT[k][c] * sw[k];
        out[OFF_ST + n0 + c] = s + sb[0];
        #pragma unroll
        for (int t = 0; t < 3; t++) {
            float da = 0.0f, db = 0.0f;
            const float* iwt = iw + t*258;
            #pragma unroll 8
            for (int k = 0; k < HH; k++) {
                float hv = s_hT[k][c];
                da += hv * iwt[k]; db += hv * iwt[128 + k];
            }
            g_dots[t][n0 + c] = da; g_dots[3+t][n0 + c] = db;
        }
    }
    __syncthreads();

    b2 = pack2(ccb1[c]);
    #pragma unroll
    for (int q = 0; q < 16; q++) acc[q] = b2;
    gemm_t<8,36>(acc, s_hT, ccw1, c, HH);
    #pragma unroll
    for (int p2 = 0; p2 < 16; p2++) {
        float2 f = unpack2(acc[p2]);
        s_tT[c][2*p2] = fmaxf(f.x, 0.0f); s_tT[c][2*p2+1] = fmaxf(f.y, 0.0f);
    }
    __syncthreads();
    if (c < 64) {
        ull bb = pack2(ccb2[c]);
        #pragma unroll
        for (int q = 0; q < 16; q++) acc[q] = bb;
        #pragma unroll 4
        for (int k = 0; k < HH; k++) {
            ull w2 = pack2(ccw2[k*64 + c]);
            const ulonglong2* r = reinterpret_cast<const ulonglong2*>(s_tT[k]);
            #pragma unroll
            for (int q = 0; q < 8; q++) {
                ulonglong2 v = r[q];
                ffma2(acc[2*q], v.x, w2); ffma2(acc[2*q+1], v.y, w2);
            }
        }
        #pragma unroll
        for (int p2 = 0; p2 < 16; p2++) {
            float2 f = unpack2(acc[p2]);
            out[OFF_CONF + (n0+2*p2)*64 + c]   = f.x;
            out[OFF_CONF + (n0+2*p2+1)*64 + c] = f.y;
        }
    }
}

__global__ void scores_kernel(const float* __restrict__ iw, const float* __restrict__ ib,
                              float* __restrict__ out) {
    int idx = blockIdx.x * blockDim.x + threadIdx.x;
    if (idx >= NN*KI) return;
    int i = idx / KI, e = idx % KI;
    const float* p = g_pos[0];
    int cnt = g_icnt[i];
    int j = g_iidx[i*KI + e];
    float mask = (e < cnt) ? 1.0f : 0.0f;
    float dx = p[3*i]-p[3*j], dy = p[3*i+1]-p[3*j+1], dz = p[3*i+2]-p[3*j+2];
    float dist = sqrtf(dx*dx + dy*dy + dz*dz + 1e-12f);
    #pragma unroll
    for (int t = 0; t < 3; t++) {
        const float* iwt = iw + t*258;
        float x = g_dots[t][i] + g_dots[3+t][j] + dist*iwt[256] + (dist/10.0f)*iwt[257] + ib[t];
        out[OFF_S + t*(NN*KI) + i*KI + e] = __fdividef(1.0f, 1.0f + __expf(-x)) * mask;
    }
}

extern "C" void kernel_launch(void* const* d_in, const int* in_sizes, int n_in,
                              void* d_out, int out_size)
{
    const float* h     = (const float*)d_in[0];
    const float* pos   = (const float*)d_in[1];
    const int*   batch = (const int*)  d_in[2];
    const float* ew1   = (const float*)d_in[3];
    const float* eb1   = (const float*)d_in[4];
    const float* ew2   = (const float*)d_in[5];
    const float* eb2   = (const float*)d_in[6];
    const float* cw1   = (const float*)d_in[7];
    const float* cb1   = (const float*)d_in[8];
    const float* cw2   = (const float*)d_in[9];
    const float* nw1   = (const float*)d_in[10];
    const float* nb1   = (const float*)d_in[11];
    const float* nw2   = (const float*)d_in[12];
    const float* nb2   = (const float*)d_in[13];
    const float* fw1   = (const float*)d_in[14];
    const float* fb1   = (const float*)d_in[15];
    const float* fw2   = (const float*)d_in[16];
    const float* fb2   = (const float*)d_in[17];
    const float* iw    = (const float*)d_in[18];
    const float* ib    = (const float*)d_in[19];
    const float* ccw1  = (const float*)d_in[20];
    const float* ccb1  = (const float*)d_in[21];
    const float* ccw2  = (const float*)d_in[22];
    const float* ccb2  = (const float*)d_in[23];
    const float* sw    = (const float*)d_in[24];
    const float* sb    = (const float*)d_in[25];
    float* out = (float*)d_out;

    cudaFuncSetAttribute(edge_mma_kernel, cudaFuncAttributeMaxDynamicSharedMemorySize, EDGE_DSM);

    setup_kernel<<<2085, 256>>>(h, pos, batch, ew2, cw1);

    const float cut2[3] = {9.0f, 36.0f, 100.0f};
    int sel = 0;
    // layer 0 pre + layer-0 neighbor search on pos[0]
    nodepre_kernel<<<NN/8, 256>>>(0, 0, 1, 0, cut2[0], batch,
                                  nw1, nb1, nw2, nb2, ew1, eb1);
    for (int l = 0; l < 6; l++) {
        edge_mma_kernel<<<NN/4, 256, EDGE_DSM>>>(sel, l, ew1 + l*257*HH + 256*HH,
                                                 eb2 + l*HH, cb1 + l*HH, cw2 + l*HH);
        int mode = (l < 5) ? 1 : 2;
        int lp = (l < 5) ? l + 1 : 0;
        // nbrk: KM search for next even layer, KI search after the last layer
        int nbrk = (l < 5) ? ((((l + 1) & 1) == 0) ? 1 : 0) : 2;
        float cc2 = (l < 5) ? cut2[(l+1)/2] : 100.0f;
        nodepre_kernel<<<NN/8, 256>>>(sel, mode, nbrk, sel ^ 1, cc2, batch,
                                      nw1 + l*256*HH, nb1 + l*HH,
                                      nw2 + l*HH*HH,  nb2 + l*HH,
                                      ew1 + lp*257*HH, eb1 + lp*HH);
        sel ^= 1;
    }
    final_tile_kernel<<<NN/32, HH>>>(fw1, fb1, fw2, fb2,
                                     ccw1, ccb1, ccw2, ccb2, sw, sb, iw, out);
    scores_kernel<<<(NN*KI + 255)/256, 256>>>(iw, ib, out);
}